// round 9
// baseline (speedup 1.0000x reference)
#include <cuda_runtime.h>
#include <cstdint>

// ======================= device scratch (no cudaMalloc allowed) =======================
__device__ float g_buf0[16*128*128*64];   // enc1 out / dt1 out
__device__ float g_buf1[16*64*64*128];
__device__ float g_buf2[16*64*64*128];
__device__ float g_tmpb[16*64*64*32];
__device__ float g_fbuf[16*64*64*128];
__device__ float g_qbuf[16*64*64*128];
__device__ float g_ehalf[512];
__device__ uint32_t g_wfrag[1u<<21];      // pre-converted tf32 weight fragments (8 MB)

__device__ __forceinline__ uint32_t f2tf32(float x) {
    uint32_t r; asm("cvt.rna.tf32.f32 %0, %1;" : "=r"(r) : "f"(x)); return r;
}
__device__ __forceinline__ void mma_tf32(float* d, const uint32_t* a, const uint32_t* b) {
    asm volatile(
        "mma.sync.aligned.m16n8k8.row.col.f32.tf32.tf32.f32 "
        "{%0,%1,%2,%3}, {%4,%5,%6,%7}, {%8,%9}, {%0,%1,%2,%3};"
        : "+f"(d[0]), "+f"(d[1]), "+f"(d[2]), "+f"(d[3])
        : "r"(a[0]), "r"(a[1]), "r"(a[2]), "r"(a[3]), "r"(b[0]), "r"(b[1]));
}

// ======================= weight prep: HWIO -> tf32 B-fragment order =======================
// Fragment per 8n x 8k tile: word = ((n%8)*4 + (k%4))*2 + (k>>2 within 8).
// Tiles: [slab s][ksBlock][nTile]. lo section (SPLIT==3) after all NPAR hi sections.
template<int CIN,int COUT,int KH,int KW,bool TRANS,int SPLIT>
__global__ void wprep(const float* __restrict__ wgt, uint32_t* __restrict__ dst)
{
    constexpr int K = TRANS ? 4*CIN : KH*KW*CIN;
    constexpr int PSZ = (K/8)*(COUT/8)*64;
    constexpr int NPAR = TRANS ? 4 : 1;
    int idx = blockIdx.x*256 + threadIdx.x;
    if (idx >= K*COUT) return;
    int k = idx / COUT, co = idx % COUT;
    int par = blockIdx.y;
    float w;
    if (TRANS) {
        int py = par >> 1, px = par & 1;
        int ci = k % CIN; int ab = k / CIN;
        int bb = ab & 1, aa = ab >> 1;
        int widx = ((2*aa + py)*KW + (2*bb + px))*CIN + ci;
        w = wgt[widx*COUT + co];
    } else {
        w = wgt[k*COUT + co];
    }
    uint32_t h = f2tf32(w);
    int s = k >> 5, kb = (k >> 3) & 3, kr = k & 7;
    int off = ((s*4 + kb)*(COUT/8) + (co >> 3))*64 + ((co & 7)*4 + (kr & 3))*2 + (kr >> 2);
    dst[par*PSZ + off] = h;
    if (SPLIT == 3)
        dst[NPAR*PSZ + par*PSZ + off] = f2tf32(w - __uint_as_float(h));
}

// ======================= fp32 tiled implicit-GEMM conv (enc1 only) =======================
template<int BM,int BN,int BK,int TM,int TN,
         int CIN,int COUT,int KH,int KW,int STRIDE,int PAD,
         int INH,int INW,int NB,
         bool RELU_IN,bool HAS_BIAS,bool ADD,bool RELU_OUT,bool TRANS>
__global__ void __launch_bounds__(256)
conv_gemm(const float* __restrict__ in, const float* __restrict__ wgt,
          const float* __restrict__ bias, const float* __restrict__ addsrc,
          float* __restrict__ out)
{
    constexpr int MH = INH / STRIDE;
    constexpr int MW = INW / STRIDE;
    constexpr int K  = KH*KW*CIN;
    constexpr int THREADS = (BM/TM)*(BN/TN);
    static_assert(THREADS == 256, "block must be 256 threads");

    __shared__ __align__(16) float As[BK][BM+4];
    __shared__ __align__(16) float Bs[BK][BN];

    const int tid = threadIdx.x;
    const int m0  = blockIdx.x * BM;
    const int n0  = blockIdx.y * BN;

    const int tcol = tid % (BN/TN);
    const int trow = tid / (BN/TN);

    float acc[TM][TN];
    #pragma unroll
    for (int i = 0; i < TM; i++)
        #pragma unroll
        for (int j = 0; j < TN; j++) acc[i][j] = 0.f;

    for (int k0 = 0; k0 < K; k0 += BK) {
        #pragma unroll
        for (int i = 0; i < (BM*BK)/THREADS; i++) {
            int l = tid + i*THREADS;
            int mloc = l / BK, kloc = l % BK;
            int m = m0 + mloc;
            int k = k0 + kloc;
            int mx = m % MW; int t = m / MW; int my = t % MH; int n = t / MH;
            float v = 0.f;
            int ci = k % CIN; int r = k / CIN;
            int kw = r % KW, kh = r / KW;
            int iy = my*STRIDE - PAD + kh;
            int ix = mx*STRIDE - PAD + kw;
            if (iy >= 0 && iy < INH && ix >= 0 && ix < INW)
                v = in[((n*INH + iy)*INW + ix)*CIN + ci];
            if (RELU_IN) v = fmaxf(v, 0.f);
            As[kloc][mloc] = v;
        }
        #pragma unroll
        for (int i = 0; i < (BK*BN)/THREADS; i++) {
            int l = tid + i*THREADS;
            int kloc = l / BN, nloc = l % BN;
            int k = k0 + kloc;
            Bs[kloc][nloc] = wgt[k*COUT + n0 + nloc];
        }
        __syncthreads();
        #pragma unroll
        for (int kk = 0; kk < BK; kk++) {
            float ra[TM], rb[TN];
            #pragma unroll
            for (int i = 0; i < TM; i += 4) {
                float4 t4 = *reinterpret_cast<const float4*>(&As[kk][trow*TM + i]);
                ra[i]=t4.x; ra[i+1]=t4.y; ra[i+2]=t4.z; ra[i+3]=t4.w;
            }
            #pragma unroll
            for (int j = 0; j < TN; j += 4) {
                float4 t4 = *reinterpret_cast<const float4*>(&Bs[kk][tcol*TN + j]);
                rb[j]=t4.x; rb[j+1]=t4.y; rb[j+2]=t4.z; rb[j+3]=t4.w;
            }
            #pragma unroll
            for (int i = 0; i < TM; i++)
                #pragma unroll
                for (int j = 0; j < TN; j++)
                    acc[i][j] += ra[i]*rb[j];
        }
        __syncthreads();
    }
    #pragma unroll
    for (int i = 0; i < TM; i++) {
        int m = m0 + trow*TM + i;
        int obase = m*COUT;
        #pragma unroll
        for (int j = 0; j < TN; j++) {
            int c = n0 + tcol*TN + j;
            float v = acc[i][j];
            if (HAS_BIAS) v += bias[c];
            if (ADD)      v += addsrc[obase + c];
            if (RELU_OUT) v = fmaxf(v, 0.f);
            out[obase + c] = v;
        }
    }
}

// ====== tf32 mma.sync implicit-GEMM conv, A in smem (ping-pong), B fragments from gmem ======
template<int CIN,int COUT,int KH,int KW,int STRIDE,int PAD,int INH,int INW,
         bool RELU_IN,bool HAS_BIAS,bool ADD,bool RELU_OUT,bool TRANS,int SPLIT>
__global__ void __launch_bounds__(256)
mma_conv4(const float* __restrict__ in, const uint32_t* __restrict__ wfrag,
          const float* __restrict__ bias, const float* __restrict__ addsrc,
          float* __restrict__ out)
{
    constexpr int MH = TRANS ? INH : INH / STRIDE;
    constexpr int MW = TRANS ? INW : INW / STRIDE;
    constexpr int K  = TRANS ? 4*CIN : KH*KW*CIN;
    constexpr int BM = 128, BK = 32, BN = COUT;
    constexpr int S  = K / BK;
    constexpr int WARPS_N = (BN >= 64) ? 2 : 1;
    constexpr int WARPS_M = 8 / WARPS_N;
    constexpr int WM = BM / WARPS_M;
    constexpr int WN = BN / WARPS_N;
    constexpr int MF = WM / 16;
    constexpr int NF = WN / 8;
    constexpr int ASTR = BK + 4;
    constexpr int A_WORDS = BM*ASTR;
    constexpr int NCOPY = (SPLIT==3 ? 2 : 1);
    constexpr int CSZ = NCOPY*A_WORDS;
    constexpr int PSZ = (K/8)*(BN/8)*64;
    constexpr int NPAR = TRANS ? 4 : 1;

    extern __shared__ __align__(16) uint32_t smem[];

    const int tid  = threadIdx.x;
    const int wid  = tid >> 5;
    const int lane = tid & 31;
    const int m0   = blockIdx.x * BM;
    const int py   = TRANS ? (int)(blockIdx.z >> 1) : 0;
    const int px   = TRANS ? (int)(blockIdx.z & 1)  : 0;
    const int wm   = wid / WARPS_N;
    const int wn   = wid % WARPS_N;
    const int lr   = lane >> 2;
    const int lc   = lane & 3;

    const uint32_t* wH = wfrag + (TRANS ? (int)blockIdx.z*PSZ : 0);
    const uint32_t* wL = wfrag + NPAR*PSZ + (TRANS ? (int)blockIdx.z*PSZ : 0);

    float acc[MF][NF][4];
    #pragma unroll
    for (int i = 0; i < MF; i++)
        #pragma unroll
        for (int j = 0; j < NF; j++)
            #pragma unroll
            for (int r = 0; r < 4; r++) acc[i][j][r] = 0.f;

    float4 aR[4];

    auto load_regs = [&](int s) {
        const int k0 = s * BK;
        #pragma unroll
        for (int it = 0; it < 4; it++) {
            int l = tid + it*256;
            int m = l >> 3, kq = l & 7;
            int k = k0 + kq*4;
            int mg = m0 + m;
            int mx = mg % MW; int t = mg / MW; int my = t % MH; int n = t / MH;
            int iy, ix, ci;
            if (TRANS) {
                ci = k % CIN; int ab = k / CIN;
                int bb = ab & 1, aa = ab >> 1;
                iy = my + py + aa - 1;
                ix = mx + px + bb - 1;
            } else {
                ci = k % CIN; int r = k / CIN;
                int kw = r % KW, kh = r / KW;
                iy = my*STRIDE - PAD + kh;
                ix = mx*STRIDE - PAD + kw;
            }
            if (iy >= 0 && iy < INH && ix >= 0 && ix < INW)
                aR[it] = *reinterpret_cast<const float4*>(&in[((n*INH + iy)*INW + ix)*CIN + ci]);
            else
                aR[it] = make_float4(0.f,0.f,0.f,0.f);
        }
    };

    auto store_regs = [&](int buf) {
        uint32_t* AsH = smem + buf*CSZ;
        uint32_t* AsL = AsH + A_WORDS;
        #pragma unroll
        for (int it = 0; it < 4; it++) {
            int l = tid + it*256;
            int m = l >> 3, kq = l & 7;
            float4 v = aR[it];
            if (RELU_IN) {
                v.x = fmaxf(v.x, 0.f); v.y = fmaxf(v.y, 0.f);
                v.z = fmaxf(v.z, 0.f); v.w = fmaxf(v.w, 0.f);
            }
            uint4 h;
            h.x = f2tf32(v.x); h.y = f2tf32(v.y); h.z = f2tf32(v.z); h.w = f2tf32(v.w);
            *reinterpret_cast<uint4*>(&AsH[m*ASTR + kq*4]) = h;
            if (SPLIT == 3) {
                uint4 lo;
                lo.x = f2tf32(v.x - __uint_as_float(h.x));
                lo.y = f2tf32(v.y - __uint_as_float(h.y));
                lo.z = f2tf32(v.z - __uint_as_float(h.z));
                lo.w = f2tf32(v.w - __uint_as_float(h.w));
                *reinterpret_cast<uint4*>(&AsL[m*ASTR + kq*4]) = lo;
            }
        }
    };

    auto compute = [&](int s, int buf) {
        const uint32_t* AsH = smem + buf*CSZ;
        const uint32_t* AsL = AsH + A_WORDS;
        #pragma unroll
        for (int ks = 0; ks < BK; ks += 8) {
            uint32_t ah[MF][4], al[MF][4];
            #pragma unroll
            for (int i = 0; i < MF; i++) {
                int r = wm*WM + i*16 + lr;
                ah[i][0] = AsH[(r    )*ASTR + ks + lc];
                ah[i][1] = AsH[(r + 8)*ASTR + ks + lc];
                ah[i][2] = AsH[(r    )*ASTR + ks + lc + 4];
                ah[i][3] = AsH[(r + 8)*ASTR + ks + lc + 4];
                if (SPLIT == 3) {
                    al[i][0] = AsL[(r    )*ASTR + ks + lc];
                    al[i][1] = AsL[(r + 8)*ASTR + ks + lc];
                    al[i][2] = AsL[(r    )*ASTR + ks + lc + 4];
                    al[i][3] = AsL[(r + 8)*ASTR + ks + lc + 4];
                }
            }
            const int tileBase = (s*4 + (ks >> 3))*(BN/8);
            #pragma unroll
            for (int j = 0; j < NF; j++) {
                int jg = wn*(WN/8) + j;
                uint2 h2 = __ldg(reinterpret_cast<const uint2*>(
                    wH + ((tileBase + jg)*64 + lane*2)));
                uint32_t bh[2] = { h2.x, h2.y };
                #pragma unroll
                for (int i = 0; i < MF; i++)
                    mma_tf32(acc[i][j], ah[i], bh);
                if (SPLIT == 3) {
                    uint2 l2 = __ldg(reinterpret_cast<const uint2*>(
                        wL + ((tileBase + jg)*64 + lane*2)));
                    uint32_t bl[2] = { l2.x, l2.y };
                    #pragma unroll
                    for (int i = 0; i < MF; i++) {
                        mma_tf32(acc[i][j], al[i], bh);
                        mma_tf32(acc[i][j], ah[i], bl);
                    }
                }
            }
        }
    };

    load_regs(0);
    store_regs(0);
    __syncthreads();
    for (int s = 0; s < S; s++) {
        if (s + 1 < S) load_regs(s + 1);
        compute(s, s & 1);
        if (s + 1 < S) store_regs((s + 1) & 1);
        __syncthreads();
    }

    // ---- epilogue ----
    #pragma unroll
    for (int i = 0; i < MF; i++) {
        int r0 = m0 + wm*WM + i*16 + lr;
        #pragma unroll
        for (int half = 0; half < 2; half++) {
            int mg = r0 + half*8;
            int obase;
            if (TRANS) {
                int mx = mg % MW; int t = mg / MW; int my = t % MH; int n = t / MH;
                obase = ((n*(2*INH) + 2*my + py)*(2*INW) + 2*mx + px)*COUT;
            } else {
                obase = mg*COUT;
            }
            #pragma unroll
            for (int j = 0; j < NF; j++) {
                int c = wn*WN + j*8 + 2*lc;
                float v0 = acc[i][j][half*2 + 0];
                float v1 = acc[i][j][half*2 + 1];
                if (HAS_BIAS) {
                    float2 bv = *reinterpret_cast<const float2*>(&bias[c]);
                    v0 += bv.x; v1 += bv.y;
                }
                if (ADD) {
                    float2 av = *reinterpret_cast<const float2*>(&addsrc[obase + c]);
                    v0 += av.x; v1 += av.y;
                }
                if (RELU_OUT) { v0 = fmaxf(v0, 0.f); v1 = fmaxf(v1, 0.f); }
                float2 ov; ov.x = v0; ov.y = v1;
                *reinterpret_cast<float2*>(&out[obase + c]) = ov;
            }
        }
    }
}

// ======================= codebook prep: fragments + half-norms =======================
__global__ void emb_prep(const float* __restrict__ emb,
                         uint32_t* __restrict__ wfH, uint32_t* __restrict__ wfL,
                         float* __restrict__ ehalf)
{
    int c = blockIdx.x;          // 512 codes
    int k = threadIdx.x;         // 128 dims
    float v = emb[c*128 + k];
    uint32_t h = f2tf32(v);
    int s = k >> 5, kb = (k >> 3) & 3, kr = k & 7;
    int off = ((s*4 + kb)*64 + (c >> 3))*64 + ((c & 7)*4 + (kr & 3))*2 + (kr >> 2);
    wfH[off] = h;
    wfL[off] = f2tf32(v - __uint_as_float(h));
    float sq = v*v;
    #pragma unroll
    for (int o = 16; o; o >>= 1) sq += __shfl_xor_sync(0xffffffffu, sq, o);
    __shared__ float red[4];
    if ((k & 31) == 0) red[k >> 5] = sq;
    __syncthreads();
    if (k == 0) ehalf[c] = 0.5f*(red[0]+red[1]+red[2]+red[3]);
}

// ======================= VQ via 3xTF32 tensor GEMM + fragment argmax =======================
__global__ void __launch_bounds__(256)
vq_mma(const float* __restrict__ f, const float* __restrict__ emb,
       const uint32_t* __restrict__ embH, const uint32_t* __restrict__ embL,
       const float* __restrict__ ehalf, float* __restrict__ q)
{
    constexpr int ASTR = 36;
    constexpr int A_WORDS = 128*ASTR;
    extern __shared__ __align__(16) uint32_t vsm[];
    uint32_t* AsH = vsm;
    uint32_t* AsL = AsH + A_WORDS;
    __shared__ float bestV[128][2];
    __shared__ int   bestI[128][2];
    __shared__ int   rowIdx[128];

    const int tid  = threadIdx.x;
    const int wid  = tid >> 5;
    const int lane = tid & 31;
    const int lr   = lane >> 2;
    const int lc   = lane & 3;
    const int m0   = blockIdx.x * 128;
    const int wm   = wid >> 1;
    const int wn   = wid & 1;

    float best[4];
    int   bidx[4];
    #pragma unroll
    for (int t = 0; t < 4; t++) { best[t] = -3.4e38f; bidx[t] = 0; }

    for (int nc = 0; nc < 4; nc++) {
        float acc[2][8][4];
        #pragma unroll
        for (int i = 0; i < 2; i++)
            #pragma unroll
            for (int j = 0; j < 8; j++)
                #pragma unroll
                for (int r = 0; r < 4; r++) acc[i][j][r] = 0.f;

        for (int s = 0; s < 4; s++) {
            const int k0 = s*32;
            #pragma unroll
            for (int it = 0; it < 4; it++) {
                int l = tid + it*256;
                int m = l >> 3, kq = l & 7;
                float4 v = *reinterpret_cast<const float4*>(&f[(m0 + m)*128 + k0 + kq*4]);
                uint4 h;
                h.x = f2tf32(v.x); h.y = f2tf32(v.y); h.z = f2tf32(v.z); h.w = f2tf32(v.w);
                *reinterpret_cast<uint4*>(&AsH[m*ASTR + kq*4]) = h;
                uint4 lo;
                lo.x = f2tf32(v.x - __uint_as_float(h.x));
                lo.y = f2tf32(v.y - __uint_as_float(h.y));
                lo.z = f2tf32(v.z - __uint_as_float(h.z));
                lo.w = f2tf32(v.w - __uint_as_float(h.w));
                *reinterpret_cast<uint4*>(&AsL[m*ASTR + kq*4]) = lo;
            }
            __syncthreads();
            #pragma unroll
            for (int ks = 0; ks < 32; ks += 8) {
                uint32_t ah[2][4], al[2][4];
                #pragma unroll
                for (int i = 0; i < 2; i++) {
                    int r = wm*32 + i*16 + lr;
                    ah[i][0] = AsH[(r    )*ASTR + ks + lc];
                    ah[i][1] = AsH[(r + 8)*ASTR + ks + lc];
                    ah[i][2] = AsH[(r    )*ASTR + ks + lc + 4];
                    ah[i][3] = AsH[(r + 8)*ASTR + ks + lc + 4];
                    al[i][0] = AsL[(r    )*ASTR + ks + lc];
                    al[i][1] = AsL[(r + 8)*ASTR + ks + lc];
                    al[i][2] = AsL[(r    )*ASTR + ks + lc + 4];
                    al[i][3] = AsL[(r + 8)*ASTR + ks + lc + 4];
                }
                const int tileBase = (s*4 + (ks >> 3))*64;
                #pragma unroll
                for (int j = 0; j < 8; j++) {
                    int jg = nc*16 + wn*8 + j;
                    uint2 h2 = __ldg(reinterpret_cast<const uint2*>(
                        embH + ((tileBase + jg)*64 + lane*2)));
                    uint2 l2 = __ldg(reinterpret_cast<const uint2*>(
                        embL + ((tileBase + jg)*64 + lane*2)));
                    uint32_t bh[2] = { h2.x, h2.y };
                    uint32_t bl[2] = { l2.x, l2.y };
                    #pragma unroll
                    for (int i = 0; i < 2; i++) {
                        mma_tf32(acc[i][j], al[i], bh);
                        mma_tf32(acc[i][j], ah[i], bl);
                        mma_tf32(acc[i][j], ah[i], bh);
                    }
                }
            }
            __syncthreads();
        }
        #pragma unroll
        for (int i = 0; i < 2; i++) {
            #pragma unroll
            for (int half = 0; half < 2; half++) {
                int slot = i*2 + half;
                #pragma unroll
                for (int j = 0; j < 8; j++) {
                    int col = nc*128 + wn*64 + j*8 + 2*lc;
                    float s0 = acc[i][j][half*2 + 0] - __ldg(&ehalf[col]);
                    float s1 = acc[i][j][half*2 + 1] - __ldg(&ehalf[col + 1]);
                    if (s0 > best[slot] || (s0 == best[slot] && col < bidx[slot]))
                        { best[slot] = s0; bidx[slot] = col; }
                    if (s1 > best[slot] || (s1 == best[slot] && col + 1 < bidx[slot]))
                        { best[slot] = s1; bidx[slot] = col + 1; }
                }
            }
        }
    }
    #pragma unroll
    for (int slot = 0; slot < 4; slot++) {
        #pragma unroll
        for (int off = 1; off < 4; off <<= 1) {
            float ov = __shfl_xor_sync(0xffffffffu, best[slot], off);
            int   oi = __shfl_xor_sync(0xffffffffu, bidx[slot], off);
            if (ov > best[slot] || (ov == best[slot] && oi < bidx[slot]))
                { best[slot] = ov; bidx[slot] = oi; }
        }
        if (lc == 0) {
            int i = slot >> 1, half = slot & 1;
            int row = wm*32 + i*16 + half*8 + lr;
            bestV[row][wn] = best[slot];
            bestI[row][wn] = bidx[slot];
        }
    }
    __syncthreads();
    for (int r = tid; r < 128; r += 256) {
        float v0 = bestV[r][0], v1 = bestV[r][1];
        int   i0 = bestI[r][0], i1 = bestI[r][1];
        rowIdx[r] = (v1 > v0 || (v1 == v0 && i1 < i0)) ? i1 : i0;
    }
    __syncthreads();
    for (int l = tid; l < 128*128; l += 256) {
        int r = l >> 7, j = l & 127;
        q[(m0 + r)*128 + j] = emb[rowIdx[r]*128 + j];
    }
}

// ======================= dt2: 4x4 s2 tconv 64->3, direct =======================
__global__ void __launch_bounds__(256)
dt2_kernel(const float* __restrict__ in,
           const float* __restrict__ wgt,
           const float* __restrict__ bias,
           float* __restrict__ out)
{
    __shared__ float ws[4*4*64*3];
    for (int l = threadIdx.x; l < 3072; l += 256) ws[l] = wgt[l];
    __syncthreads();

    const int py = blockIdx.z >> 1, px = blockIdx.z & 1;
    const int m = blockIdx.x * 256 + threadIdx.x;
    const int xq = m & 127; int t = m >> 7; const int yq = t & 127; const int n = t >> 7;

    float a0 = __ldg(&bias[0]), a1 = __ldg(&bias[1]), a2 = __ldg(&bias[2]);
    #pragma unroll
    for (int aa = 0; aa < 2; aa++) {
        #pragma unroll
        for (int bb = 0; bb < 2; bb++) {
            int iy = yq + py + aa - 1;
            int ix = xq + px + bb - 1;
            if (iy < 0 || iy >= 128 || ix < 0 || ix >= 128) continue;
            const float* ip = in + ((n*128 + iy)*128 + ix)*64;
            const float* wp = ws + ((2*aa + py)*4 + (2*bb + px))*64*3;
            #pragma unroll
            for (int ci = 0; ci < 64; ci += 4) {
                float4 v = *reinterpret_cast<const float4*>(ip + ci);
                const float* w0 = wp + ci*3;
                a0 += v.x*w0[0];  a1 += v.x*w0[1];  a2 += v.x*w0[2];
                a0 += v.y*w0[3];  a1 += v.y*w0[4];  a2 += v.y*w0[5];
                a0 += v.z*w0[6];  a1 += v.z*w0[7];  a2 += v.z*w0[8];
                a0 += v.w*w0[9];  a1 += v.w*w0[10]; a2 += v.w*w0[11];
            }
        }
    }
    const int oy = 2*yq + py, ox = 2*xq + px;
    float* op = out + ((n*256 + oy)*256 + ox)*3;
    op[0] = a0; op[1] = a1; op[2] = a2;
}

// ======================= host launcher =======================
extern "C" void kernel_launch(void* const* d_in, const int* in_sizes, int n_in,
                              void* d_out, int out_size)
{
    (void)in_sizes; (void)n_in;
    const float* x       = (const float*)d_in[0];
    const float* emb     = (const float*)d_in[1];
    const float* enc_w1  = (const float*)d_in[2];
    const float* enc_b1  = (const float*)d_in[3];
    const float* enc_w2  = (const float*)d_in[4];
    const float* enc_b2  = (const float*)d_in[5];
    const float* enc_w3  = (const float*)d_in[6];
    const float* enc_b3  = (const float*)d_in[7];
    const float* erb1_w1 = (const float*)d_in[8];
    const float* erb1_w2 = (const float*)d_in[9];
    const float* erb2_w1 = (const float*)d_in[10];
    const float* erb2_w2 = (const float*)d_in[11];
    const float* dec_w   = (const float*)d_in[12];
    const float* dec_b   = (const float*)d_in[13];
    const float* drb1_w1 = (const float*)d_in[14];
    const float* drb1_w2 = (const float*)d_in[15];
    const float* drb2_w1 = (const float*)d_in[16];
    const float* drb2_w2 = (const float*)d_in[17];
    const float* dt1_w   = (const float*)d_in[18];
    const float* dt1_b   = (const float*)d_in[19];
    const float* dt2_w   = (const float*)d_in[20];
    const float* dt2_b   = (const float*)d_in[21];

    float* out = (float*)d_out;
    const int YS = 16*256*256*3;
    const int FS = 16*64*64*128;

    float *buf0,*buf1,*buf2,*tmpb,*ehalf,*fb,*qb;
    uint32_t* wf;
    cudaGetSymbolAddress((void**)&buf0,  g_buf0);
    cudaGetSymbolAddress((void**)&buf1,  g_buf1);
    cudaGetSymbolAddress((void**)&buf2,  g_buf2);
    cudaGetSymbolAddress((void**)&tmpb,  g_tmpb);
    cudaGetSymbolAddress((void**)&ehalf, g_ehalf);
    cudaGetSymbolAddress((void**)&fb,    g_fbuf);
    cudaGetSymbolAddress((void**)&qb,    g_qbuf);
    cudaGetSymbolAddress((void**)&wf,    g_wfrag);

    const bool full = (out_size >= YS + 2*FS);
    float* fptr = full ? (out + YS)      : fb;
    float* qptr = full ? (out + YS + FS) : qb;

    dim3 b(256);

    // ---- weight fragment offsets (words), CORRECTED sizes ----
    // ENC2: K=1024,COUT=128 -> PSZ=131072, x2 = 262144
    // ENC3: K=1152,COUT=128 -> PSZ=147456, x2 = 294912
    // E*W1: K=1152,COUT=32  -> PSZ=36864,  x2 = 73728
    // E*W2: K=32,  COUT=128 -> PSZ=4096,   x2 = 8192
    // DEC : 147456 (hi only); D*W1: 36864; D*W2: 4096
    // DT1 : 4 parities x PSZ=32768 = 131072 (hi only)
    // EMB : 65536 hi + 65536 lo
    const int O_ENC2 = 0;
    const int O_ENC3 = 262144;
    const int O_E1W1 = 557056;
    const int O_E1W2 = 630784;
    const int O_E2W1 = 638976;
    const int O_E2W2 = 712704;
    const int O_DEC  = 720896;
    const int O_D1W1 = 868352;
    const int O_D1W2 = 905216;
    const int O_D2W1 = 909312;
    const int O_D2W2 = 946176;
    const int O_DT1  = 950272;
    const int O_EMBH = 1081344;
    const int O_EMBL = 1146880;   // end 1212416 < 2^21

    // ---- prep: convert all weights to fragment order (grids cover FULL K*COUT) ----
    wprep<64,128,4,4,false,3><<<dim3((1024*128+255)/256,1), b>>>(enc_w2, wf + O_ENC2);
    wprep<128,128,3,3,false,3><<<dim3((1152*128+255)/256,1), b>>>(enc_w3, wf + O_ENC3);
    wprep<128,32,3,3,false,3><<<dim3((1152*32+255)/256,1), b>>>(erb1_w1, wf + O_E1W1);
    wprep<32,128,1,1,false,3><<<dim3((32*128+255)/256,1), b>>>(erb1_w2, wf + O_E1W2);
    wprep<128,32,3,3,false,3><<<dim3((1152*32+255)/256,1), b>>>(erb2_w1, wf + O_E2W1);
    wprep<32,128,1,1,false,3><<<dim3((32*128+255)/256,1), b>>>(erb2_w2, wf + O_E2W2);
    wprep<128,128,3,3,false,1><<<dim3((1152*128+255)/256,1), b>>>(dec_w, wf + O_DEC);
    wprep<128,32,3,3,false,1><<<dim3((1152*32+255)/256,1), b>>>(drb1_w1, wf + O_D1W1);
    wprep<32,128,1,1,false,1><<<dim3((32*128+255)/256,1), b>>>(drb1_w2, wf + O_D1W2);
    wprep<128,32,3,3,false,1><<<dim3((1152*32+255)/256,1), b>>>(drb2_w1, wf + O_D2W1);
    wprep<32,128,1,1,false,1><<<dim3((32*128+255)/256,1), b>>>(drb2_w2, wf + O_D2W2);
    wprep<128,64,4,4,true,1><<<dim3((512*64+255)/256,4), b>>>(dt1_w, wf + O_DT1);
    emb_prep<<<512,128>>>(emb, wf + O_EMBH, wf + O_EMBL, ehalf);

    // ---- kernel instances + smem (A only; all double-buffered) ----
    const int SM3 = 2*2*128*36*4;   // 73728
    const int SM1 = 2*1*128*36*4;   // 36864
    const int SMV = 2*128*36*4;     // 36864

    auto kEnc2 = mma_conv4<64,128,4,4,2,1, 128,128, false,true,false,true,false,3>;
    auto kEnc3 = mma_conv4<128,128,3,3,1,1, 64,64, false,true,false,false,false,3>;
    auto kEw1  = mma_conv4<128,32, 3,3,1,1, 64,64, true,false,false,true,false,3>;
    auto kEw2  = mma_conv4<32,128, 1,1,1,0, 64,64, false,false,true,false,false,3>;
    auto kEw2R = mma_conv4<32,128, 1,1,1,0, 64,64, false,false,true,true,false,3>;
    auto kDec  = mma_conv4<128,128,3,3,1,1, 64,64, false,true,false,false,false,1>;
    auto kDw1  = mma_conv4<128,32, 3,3,1,1, 64,64, true,false,false,true,false,1>;
    auto kDw2  = mma_conv4<32,128, 1,1,1,0, 64,64, false,false,true,false,false,1>;
    auto kDw2R = mma_conv4<32,128, 1,1,1,0, 64,64, false,false,true,true,false,1>;
    auto kDt1  = mma_conv4<128,64, 4,4,2,0, 64,64, false,true,false,true,true,1>;

    cudaFuncSetAttribute(kEnc2, cudaFuncAttributeMaxDynamicSharedMemorySize, SM3);
    cudaFuncSetAttribute(kEnc3, cudaFuncAttributeMaxDynamicSharedMemorySize, SM3);
    cudaFuncSetAttribute(kEw1,  cudaFuncAttributeMaxDynamicSharedMemorySize, SM3);
    cudaFuncSetAttribute(kEw2,  cudaFuncAttributeMaxDynamicSharedMemorySize, SM3);
    cudaFuncSetAttribute(kEw2R, cudaFuncAttributeMaxDynamicSharedMemorySize, SM3);
    cudaFuncSetAttribute(kDec,  cudaFuncAttributeMaxDynamicSharedMemorySize, SM1);
    cudaFuncSetAttribute(kDw1,  cudaFuncAttributeMaxDynamicSharedMemorySize, SM1);
    cudaFuncSetAttribute(kDw2,  cudaFuncAttributeMaxDynamicSharedMemorySize, SM1);
    cudaFuncSetAttribute(kDw2R, cudaFuncAttributeMaxDynamicSharedMemorySize, SM1);
    cudaFuncSetAttribute(kDt1,  cudaFuncAttributeMaxDynamicSharedMemorySize, SM1);
    cudaFuncSetAttribute(vq_mma, cudaFuncAttributeMaxDynamicSharedMemorySize, SMV);

    // ---- encoder (3xTF32, ~fp32 precision -> argmin-exact) ----
    conv_gemm<64,64,16,4,4,  3,64,4,4,2,1, 256,256,16, false,true,false,true,false>
        <<<dim3(4096,1,1),b>>>(x, enc_w1, enc_b1, nullptr, buf0);
    kEnc2<<<dim3(512,1,1), b, SM3>>>(buf0, wf + O_ENC2, enc_b2, nullptr, buf1);
    kEnc3<<<dim3(512,1,1), b, SM3>>>(buf1, wf + O_ENC3, enc_b3, nullptr, buf2);
    kEw1 <<<dim3(512,1,1), b, SM3>>>(buf2, wf + O_E1W1, nullptr, nullptr, tmpb);
    kEw2 <<<dim3(512,1,1), b, SM3>>>(tmpb, wf + O_E1W2, nullptr, buf2, buf2);
    kEw1 <<<dim3(512,1,1), b, SM3>>>(buf2, wf + O_E2W1, nullptr, nullptr, tmpb);
    kEw2R<<<dim3(512,1,1), b, SM3>>>(tmpb, wf + O_E2W2, nullptr, buf2, fptr);

    // ---- VQ (3xTF32 scores, fp32 norms, full-codebook argmax) ----
    vq_mma<<<512, b, SMV>>>(fptr, emb, wf + O_EMBH, wf + O_EMBL, ehalf, qptr);

    // ---- decoder (single-pass tf32) ----
    kDec <<<dim3(512,1,1), b, SM1>>>(qptr, wf + O_DEC, dec_b, nullptr, buf1);
    kDw1 <<<dim3(512,1,1), b, SM1>>>(buf1, wf + O_D1W1, nullptr, nullptr, tmpb);
    kDw2 <<<dim3(512,1,1), b, SM1>>>(tmpb, wf + O_D1W2, nullptr, buf1, buf1);
    kDw1 <<<dim3(512,1,1), b, SM1>>>(buf1, wf + O_D2W1, nullptr, nullptr, tmpb);
    kDw2R<<<dim3(512,1,1), b, SM1>>>(tmpb, wf + O_D2W2, nullptr, buf1, buf2);
    kDt1 <<<dim3(512,1,4), b, SM1>>>(buf2, wf + O_DT1, dt1_b, nullptr, buf0);

    dt2_kernel<<<dim3(1024,1,4),b>>>(buf0, dt2_w, dt2_b, out);
}